// round 2
// baseline (speedup 1.0000x reference)
#include <cuda_runtime.h>
#include <cuda_bf16.h>

// Shape: sequence_output [B=8, S=4096, H=1024] f32, sent_token_mask [B,S] int32.
// Output: concat f32 buffer [features (B*S*H) | segment_ids (B*S)].
//
// Bottleneck: pure HBM stream (268 MB). This version targets higher DRAM
// utilization: 256-thread blocks (better occupancy than regs=64@1024thr),
// unroll-4 batched loads (MLP_p1=4), and .cs streaming hints (no L2 reuse
// exists -- 134 MB working set vs 126 MB L2).

#define COPY_THREADS 256
#define COPY_BLOCKS  1024
#define SCAN_THREADS 256
#define MAX_B 64

__global__ __launch_bounds__(COPY_THREADS)
void sent_feat_fused_kernel(const float4* __restrict__ src,
                            float4* __restrict__ dst,
                            long long n4,
                            const int* __restrict__ labels,
                            float* __restrict__ out_ids,
                            int B, int S, int n_tok)
{
    if (blockIdx.x == gridDim.x - 1) {
        // ---------------- segment-id scan (single 256-thread block) ----------
        __shared__ int sums[SCAN_THREADS];
        __shared__ int extra_off[MAX_B];

        const int tid  = threadIdx.x;
        const int per  = n_tok / SCAN_THREADS;      // 128 for this shape
        const int base = tid * per;

        // Pass 1: thread-local count of (label == 0), vectorized.
        const int4* lab4 = reinterpret_cast<const int4*>(labels + base);
        int s = 0;
        #pragma unroll 8
        for (int v = 0; v < per / 4; v++) {
            int4 q = lab4[v];
            s += (q.x == 0) + (q.y == 0) + (q.z == 0) + (q.w == 0);
        }
        sums[tid] = s;

        // Per-batch "extra" exclusive offsets (B tiny; thread 0 serial).
        if (tid == 0) {
            int acc = 0;
            for (int b = 0; b < B && b < MAX_B; b++) {
                extra_off[b] = acc;
                acc += (labels[b * S + S - 1] == 1);
            }
        }
        __syncthreads();

        // Hillis-Steele inclusive scan over 256 thread sums.
        #pragma unroll
        for (int off = 1; off < SCAN_THREADS; off <<= 1) {
            int v   = sums[tid];
            int add = (tid >= off) ? sums[tid - off] : 0;
            __syncthreads();
            sums[tid] = v + add;
            __syncthreads();
        }

        // per (=128) divides S, so each thread stays within one batch.
        int run = (sums[tid] - s) + extra_off[base / S];

        // Pass 2: re-read labels (L2-hot), emit id BEFORE incrementing.
        #pragma unroll 8
        for (int v = 0; v < per / 4; v++) {
            int4 q = lab4[v];
            int gi = base + v * 4;
            out_ids[gi + 0] = (float)run; run += (q.x == 0);
            out_ids[gi + 1] = (float)run; run += (q.y == 0);
            out_ids[gi + 2] = (float)run; run += (q.z == 0);
            out_ids[gi + 3] = (float)run; run += (q.w == 0);
        }
    } else {
        // ---------------- bulk feature copy ----------------
        // Grid-stride, unroll-4 with batched independent loads, streaming hints.
        long long i       = (long long)blockIdx.x * COPY_THREADS + threadIdx.x;
        long long stride  = (long long)COPY_BLOCKS * COPY_THREADS;   // 2^18
        long long stride4 = 4 * stride;

        for (; i + 3 * stride < n4; i += stride4) {
            float4 a = __ldcs(&src[i]);
            float4 b = __ldcs(&src[i + stride]);
            float4 c = __ldcs(&src[i + 2 * stride]);
            float4 d = __ldcs(&src[i + 3 * stride]);
            __stcs(&dst[i],              a);
            __stcs(&dst[i + stride],     b);
            __stcs(&dst[i + 2 * stride], c);
            __stcs(&dst[i + 3 * stride], d);
        }
        for (; i < n4; i += stride) {
            __stcs(&dst[i], __ldcs(&src[i]));
        }
    }
}

extern "C" void kernel_launch(void* const* d_in, const int* in_sizes, int n_in,
                              void* d_out, int out_size)
{
    const float* seq    = (const float*)d_in[0];
    const int*   labels = (const int*)d_in[1];
    float*       out    = (float*)d_out;

    const long long n_feat = in_sizes[0];   // B*S*H = 33,554,432
    const int       n_tok  = in_sizes[1];   // B*S   = 32,768
    const int       S      = 4096;
    const int       B      = n_tok / S;

    const long long n4 = n_feat / 4;        // 8,388,608 float4

    sent_feat_fused_kernel<<<COPY_BLOCKS + 1, COPY_THREADS>>>(
        (const float4*)seq, (float4*)out, n4,
        labels, out + n_feat, B, S, n_tok);
}

// round 3
// speedup vs baseline: 1.2146x; 1.2146x over previous
#include <cuda_runtime.h>
#include <cuda_bf16.h>

// Shape: sequence_output [B=8, S=4096, H=1024] f32, sent_token_mask [B,S] int32.
// Output: concat f32 buffer [features (B*S*H) | segment_ids (B*S)].
//
// R2 lesson: huge-stride batched loads (4MB apart) tanked DRAM to 36%.
// This version: block-contiguous chunks, unroll-4 with SMALL offsets
// (+4KB apart) -> MLP=4 with dense locality. No cache hints.

#define COPY_THREADS 256
#define COPY_BLOCKS  1024            // n4 = 2^23 -> 8192 float4 (128 KB) per block
#define SCAN_THREADS 256
#define MAX_B 64

__global__ __launch_bounds__(COPY_THREADS)
void sent_feat_fused_kernel(const float4* __restrict__ src,
                            float4* __restrict__ dst,
                            long long n4,
                            const int* __restrict__ labels,
                            float* __restrict__ out_ids,
                            int B, int S, int n_tok)
{
    if (blockIdx.x == gridDim.x - 1) {
        // ---------------- segment-id scan (single 256-thread block) ----------
        __shared__ int sums[SCAN_THREADS];
        __shared__ int extra_off[MAX_B];

        const int tid  = threadIdx.x;
        const int per  = n_tok / SCAN_THREADS;      // 128 for this shape
        const int base = tid * per;

        // Pass 1: thread-local count of (label == 0), vectorized.
        const int4* lab4 = reinterpret_cast<const int4*>(labels + base);
        int s = 0;
        #pragma unroll 8
        for (int v = 0; v < per / 4; v++) {
            int4 q = lab4[v];
            s += (q.x == 0) + (q.y == 0) + (q.z == 0) + (q.w == 0);
        }
        sums[tid] = s;

        // Per-batch "extra" exclusive offsets (B tiny; thread 0 serial).
        if (tid == 0) {
            int acc = 0;
            for (int b = 0; b < B && b < MAX_B; b++) {
                extra_off[b] = acc;
                acc += (labels[b * S + S - 1] == 1);
            }
        }
        __syncthreads();

        // Hillis-Steele inclusive scan over 256 thread sums.
        #pragma unroll
        for (int off = 1; off < SCAN_THREADS; off <<= 1) {
            int v   = sums[tid];
            int add = (tid >= off) ? sums[tid - off] : 0;
            __syncthreads();
            sums[tid] = v + add;
            __syncthreads();
        }

        // per (=128) divides S, so each thread stays within one batch.
        int run = (sums[tid] - s) + extra_off[base / S];

        // Pass 2: re-read labels (L2-hot), emit id BEFORE incrementing.
        #pragma unroll 8
        for (int v = 0; v < per / 4; v++) {
            int4 q = lab4[v];
            int gi = base + v * 4;
            out_ids[gi + 0] = (float)run; run += (q.x == 0);
            out_ids[gi + 1] = (float)run; run += (q.y == 0);
            out_ids[gi + 2] = (float)run; run += (q.z == 0);
            out_ids[gi + 3] = (float)run; run += (q.w == 0);
        }
    } else {
        // ---------------- bulk feature copy ----------------
        // Each block: contiguous chunk of n4/COPY_BLOCKS float4.
        // Unroll-4 with +COPY_THREADS offsets: 4 independent loads 4KB apart.
        const long long chunk = n4 / COPY_BLOCKS;             // 8192
        long long i   = (long long)blockIdx.x * chunk + threadIdx.x;
        const long long end = (long long)blockIdx.x * chunk + chunk;

        #pragma unroll 2
        for (; i + 3 * COPY_THREADS < end; i += 4 * COPY_THREADS) {
            float4 a = src[i];
            float4 b = src[i + COPY_THREADS];
            float4 c = src[i + 2 * COPY_THREADS];
            float4 d = src[i + 3 * COPY_THREADS];
            dst[i]                    = a;
            dst[i + COPY_THREADS]     = b;
            dst[i + 2 * COPY_THREADS] = c;
            dst[i + 3 * COPY_THREADS] = d;
        }
        for (; i < end; i += COPY_THREADS) {
            dst[i] = src[i];
        }
    }
}

extern "C" void kernel_launch(void* const* d_in, const int* in_sizes, int n_in,
                              void* d_out, int out_size)
{
    const float* seq    = (const float*)d_in[0];
    const int*   labels = (const int*)d_in[1];
    float*       out    = (float*)d_out;

    const long long n_feat = in_sizes[0];   // B*S*H = 33,554,432
    const int       n_tok  = in_sizes[1];   // B*S   = 32,768
    const int       S      = 4096;
    const int       B      = n_tok / S;

    const long long n4 = n_feat / 4;        // 8,388,608 float4

    sent_feat_fused_kernel<<<COPY_BLOCKS + 1, COPY_THREADS>>>(
        (const float4*)seq, (float4*)out, n4,
        labels, out + n_feat, B, S, n_tok);
}

// round 4
// speedup vs baseline: 1.4164x; 1.1661x over previous
#include <cuda_runtime.h>
#include <cuda_bf16.h>

// Shape: sequence_output [B=8, S=4096, H=1024] f32, sent_token_mask [B,S] int32.
// Output: concat f32 buffer [features (B*S*H) | segment_ids (B*S)].
//
// Copy strategy (R1/R2/R3 evidence): dense wave-sweep grid-stride access wins;
// scattered batched loads lose. This round: keep the dense sweep, raise
// occupancy (512-thr blocks -> 3 blocks/SM vs R1's 1), one-wave persistent
// grid, unroll-2 with the pair offset = total thread count (adjacent waves,
// density preserved).

#define THREADS      512
#define COPY_BLOCKS  444     // 148 SMs * 3 blocks/SM -> one resident wave
#define MAX_B 64

__global__ __launch_bounds__(THREADS)
void sent_feat_fused_kernel(const float4* __restrict__ src,
                            float4* __restrict__ dst,
                            long long n4,
                            const int* __restrict__ labels,
                            float* __restrict__ out_ids,
                            int B, int S, int n_tok)
{
    if (blockIdx.x == gridDim.x - 1) {
        // ---------------- segment-id scan (single 512-thread block) ----------
        __shared__ int sums[THREADS];
        __shared__ int extra_off[MAX_B];

        const int tid  = threadIdx.x;
        const int per  = n_tok / THREADS;           // 64 for this shape
        const int base = tid * per;

        // Pass 1: thread-local count of (label == 0), vectorized int4.
        const int4* lab4 = reinterpret_cast<const int4*>(labels + base);
        int s = 0;
        #pragma unroll
        for (int v = 0; v < 64 / 4; v++) {
            int4 q = lab4[v];
            s += (q.x == 0) + (q.y == 0) + (q.z == 0) + (q.w == 0);
        }
        sums[tid] = s;

        // Per-batch "extra" exclusive offsets (B tiny; thread 0 serial).
        if (tid == 0) {
            int acc = 0;
            for (int b = 0; b < B && b < MAX_B; b++) {
                extra_off[b] = acc;
                acc += (labels[b * S + S - 1] == 1);
            }
        }
        __syncthreads();

        // Hillis-Steele inclusive scan over 512 thread sums.
        #pragma unroll
        for (int off = 1; off < THREADS; off <<= 1) {
            int v   = sums[tid];
            int add = (tid >= off) ? sums[tid - off] : 0;
            __syncthreads();
            sums[tid] = v + add;
            __syncthreads();
        }

        // per (=64) divides S, so each thread stays within one batch.
        int run = (sums[tid] - s) + extra_off[base / S];

        // Pass 2: re-read labels (L2-hot), emit id BEFORE incrementing.
        #pragma unroll
        for (int v = 0; v < 64 / 4; v++) {
            int4 q = lab4[v];
            int gi = base + v * 4;
            out_ids[gi + 0] = (float)run; run += (q.x == 0);
            out_ids[gi + 1] = (float)run; run += (q.y == 0);
            out_ids[gi + 2] = (float)run; run += (q.z == 0);
            out_ids[gi + 3] = (float)run; run += (q.w == 0);
        }
    } else {
        // ---------------- bulk feature copy ----------------
        // Dense wave sweep: all threads form one contiguous window of
        // T*16 bytes (~3.6 MB) that sweeps the buffer. Unroll-2 pairs two
        // ADJACENT waves -> 2 in-flight loads/thread, density intact.
        const long long T = (long long)COPY_BLOCKS * THREADS;   // 227,328
        long long i = (long long)blockIdx.x * THREADS + threadIdx.x;

        for (; i + T < n4; i += 2 * T) {
            float4 a = src[i];
            float4 b = src[i + T];
            dst[i]     = a;
            dst[i + T] = b;
        }
        for (; i < n4; i += T) {
            dst[i] = src[i];
        }
    }
}

extern "C" void kernel_launch(void* const* d_in, const int* in_sizes, int n_in,
                              void* d_out, int out_size)
{
    const float* seq    = (const float*)d_in[0];
    const int*   labels = (const int*)d_in[1];
    float*       out    = (float*)d_out;

    const long long n_feat = in_sizes[0];   // B*S*H = 33,554,432
    const int       n_tok  = in_sizes[1];   // B*S   = 32,768
    const int       S      = 4096;
    const int       B      = n_tok / S;

    const long long n4 = n_feat / 4;        // 8,388,608 float4

    sent_feat_fused_kernel<<<COPY_BLOCKS + 1, THREADS>>>(
        (const float4*)seq, (float4*)out, n4,
        labels, out + n_feat, B, S, n_tok);
}